// round 4
// baseline (speedup 1.0000x reference)
#include <cuda_runtime.h>

#define BB 4
#define CC 64
#define HH 512
#define WW 512
#define HWSZ (HH * WW)            // 262144
#define NPIX (BB * HWSZ)          // 1048576
#define NQUAD (NPIX / 4)          // 262144
#define N_ORI 20
#define NBLOCKS (NQUAD / 256)     // 1024
#define IGN 255

// Scratch (allocation-free per harness rules). Statically zeroed for first
// run; the last block of each run resets them, keeping graph replays
// deterministic.
__device__ double g_sum = 0.0;
__device__ unsigned long long g_cnt = 0ull;
__device__ unsigned int g_ticket = 0u;

__global__ __launch_bounds__(256, 6) void uce_kernel(
    const float* __restrict__ inp,   // [B, C, H, W] f32
    const int* __restrict__ tgt,     // [B, H, W] int32
    const int* __restrict__ gid,     // [C] int32
    float* __restrict__ out)
{
    // Per-origin-class channel bitmasks, as two 32-bit halves (lo: c<32, hi: c>=32)
    __shared__ unsigned int smask_lo[N_ORI];
    __shared__ unsigned int smask_hi[N_ORI];
    int tid = threadIdx.x;
    if (tid < N_ORI) { smask_lo[tid] = 0u; smask_hi[tid] = 0u; }
    __syncthreads();
    if (tid < CC) {
        int g = gid[tid];
        if (g >= 0 && g < N_ORI) {
            if (tid < 32) atomicOr(&smask_lo[g], 1u << tid);
            else          atomicOr(&smask_hi[g], 1u << (tid - 32));
        }
    }
    __syncthreads();

    int q = blockIdx.x * 256 + tid;          // quad index (4 pixels/thread)
    float lsum = 0.0f;
    int   lcnt = 0;

    {
        int p  = q << 2;
        int b  = p >> 18;                    // p / HWSZ
        int hw = p & (HWSZ - 1);             // multiple of 4 -> float4 aligned
        const float* base = inp + (size_t)b * (CC * HWSZ) + hw;

        int4 t = *reinterpret_cast<const int4*>(tgt + p);

        bool v0 = (unsigned)t.x < N_ORI;
        bool v1 = (unsigned)t.y < N_ORI;
        bool v2 = (unsigned)t.z < N_ORI;
        bool v3 = (unsigned)t.w < N_ORI;

        unsigned ml0 = v0 ? smask_lo[t.x] : 0u, mh0 = v0 ? smask_hi[t.x] : 0u;
        unsigned ml1 = v1 ? smask_lo[t.y] : 0u, mh1 = v1 ? smask_hi[t.y] : 0u;
        unsigned ml2 = v2 ? smask_lo[t.z] : 0u, mh2 = v2 ? smask_hi[t.z] : 0u;
        unsigned ml3 = v3 ? smask_lo[t.w] : 0u, mh3 = v3 ? smask_hi[t.w] : 0u;

        float a0 = 0.f, a1 = 0.f, a2 = 0.f, a3 = 0.f;   // all-channel sums
        float s0 = 0.f, s1 = 0.f, s2 = 0.f, s3 = 0.f;   // target-group sums

        #pragma unroll 8
        for (int c = 0; c < 32; ++c) {
            float4 v = __ldcs(reinterpret_cast<const float4*>(base + (size_t)c * HWSZ));
            float e0 = __expf(v.x), e1 = __expf(v.y);
            float e2 = __expf(v.z), e3 = __expf(v.w);
            a0 += e0; a1 += e1; a2 += e2; a3 += e3;
            unsigned bit = 1u << c;
            if (ml0 & bit) s0 += e0;
            if (ml1 & bit) s1 += e1;
            if (ml2 & bit) s2 += e2;
            if (ml3 & bit) s3 += e3;
        }
        #pragma unroll 8
        for (int c = 0; c < 32; ++c) {
            float4 v = __ldcs(reinterpret_cast<const float4*>(base + (size_t)(c + 32) * HWSZ));
            float e0 = __expf(v.x), e1 = __expf(v.y);
            float e2 = __expf(v.z), e3 = __expf(v.w);
            a0 += e0; a1 += e1; a2 += e2; a3 += e3;
            unsigned bit = 1u << c;
            if (mh0 & bit) s0 += e0;
            if (mh1 & bit) s1 += e1;
            if (mh2 & bit) s2 += e2;
            if (mh3 & bit) s3 += e3;
        }

        // -(log(s_t) - log(s_all)) = log(s_all) - log(s_t)
        if (v0) { lsum += __logf(a0) - __logf(s0); lcnt++; }
        if (v1) { lsum += __logf(a1) - __logf(s1); lcnt++; }
        if (v2) { lsum += __logf(a2) - __logf(s2); lcnt++; }
        if (v3) { lsum += __logf(a3) - __logf(s3); lcnt++; }
    }

    // Warp reduce
    #pragma unroll
    for (int o = 16; o > 0; o >>= 1) {
        lsum += __shfl_down_sync(0xFFFFFFFFu, lsum, o);
        lcnt += __shfl_down_sync(0xFFFFFFFFu, lcnt, o);
    }

    __shared__ float wsum[8];
    __shared__ int   wcnt[8];
    int wid = tid >> 5;
    int lid = tid & 31;
    if (lid == 0) { wsum[wid] = lsum; wcnt[wid] = lcnt; }
    __syncthreads();

    __shared__ bool s_last;
    if (tid == 0) {
        float bs = 0.f; int bc = 0;
        #pragma unroll
        for (int w = 0; w < 8; ++w) { bs += wsum[w]; bc += wcnt[w]; }
        atomicAdd(&g_sum, (double)bs);
        atomicAdd(&g_cnt, (unsigned long long)bc);
        __threadfence();
        unsigned int ticket = atomicAdd(&g_ticket, 1u);
        s_last = (ticket == NBLOCKS - 1);
    }
    __syncthreads();

    if (s_last && tid == 0) {
        double sum = atomicAdd(&g_sum, 0.0);                    // acquire-read
        unsigned long long n = atomicAdd(&g_cnt, 0ull);
        if (n < 1ull) n = 1ull;
        out[0] = (float)(sum / (double)n);
        // Reset scratch for the next graph replay (deterministic).
        g_sum = 0.0;
        g_cnt = 0ull;
        __threadfence();
        g_ticket = 0u;
    }
}

extern "C" void kernel_launch(void* const* d_in, const int* in_sizes, int n_in,
                              void* d_out, int out_size) {
    const float* inp = (const float*)d_in[0];
    const int*   tgt = (const int*)d_in[1];
    const int*   gid = (const int*)d_in[2];
    float*       out = (float*)d_out;

    uce_kernel<<<NBLOCKS, 256>>>(inp, tgt, gid, out);
}

// round 5
// speedup vs baseline: 1.1557x; 1.1557x over previous
#include <cuda_runtime.h>

#define BB 4
#define CC 64
#define HH 512
#define WW 512
#define HWSZ (HH * WW)            // 262144
#define NPIX (BB * HWSZ)          // 1048576
#define NQUAD (NPIX / 4)          // 262144
#define N_ORI 20
#define NBLOCKS (NQUAD / 256)     // 1024
#define STAGES 8
#define IGN 255

// Scratch (allocation-free per harness rules). Statically zeroed for first
// run; the last block of each run resets them, keeping graph replays
// deterministic.
__device__ double g_sum = 0.0;
__device__ unsigned long long g_cnt = 0ull;
__device__ unsigned int g_ticket = 0u;

__device__ __forceinline__ void cp_async16(unsigned int saddr, const void* gptr) {
    asm volatile("cp.async.cg.shared.global [%0], [%1], 16;\n"
                 :: "r"(saddr), "l"(gptr) : "memory");
}
__device__ __forceinline__ void cp_commit() {
    asm volatile("cp.async.commit_group;\n" ::: "memory");
}
template <int N>
__device__ __forceinline__ void cp_wait() {
    asm volatile("cp.async.wait_group %0;\n" :: "n"(N) : "memory");
}

__global__ __launch_bounds__(256) void uce_kernel(
    const float* __restrict__ inp,   // [B, C, H, W] f32
    const int* __restrict__ tgt,     // [B, H, W] int32
    const int* __restrict__ gid,     // [C] int32
    float* __restrict__ out)
{
    __shared__ __align__(16) float4 sbuf[STAGES * 256];   // 32 KB ring
    __shared__ unsigned int smask_lo[N_ORI];
    __shared__ unsigned int smask_hi[N_ORI];

    int tid = threadIdx.x;
    if (tid < N_ORI) { smask_lo[tid] = 0u; smask_hi[tid] = 0u; }
    __syncthreads();
    if (tid < CC) {
        int g = gid[tid];
        if (g >= 0 && g < N_ORI) {
            if (tid < 32) atomicOr(&smask_lo[g], 1u << tid);
            else          atomicOr(&smask_hi[g], 1u << (tid - 32));
        }
    }
    __syncthreads();

    int q = blockIdx.x * 256 + tid;          // quad index (4 pixels/thread)
    int p  = q << 2;
    int b  = p >> 18;                        // p / HWSZ
    int hw = p & (HWSZ - 1);                 // multiple of 4 -> float4 aligned
    const float* base = inp + (size_t)b * (CC * HWSZ) + hw;

    // This thread's slot in stage 0 (stage s = +s*4096 bytes)
    unsigned int slot0 = (unsigned int)__cvta_generic_to_shared(&sbuf[tid]);

    // Prologue: fill all stages (channels 0..STAGES-1)
    #pragma unroll
    for (int s = 0; s < STAGES; ++s) {
        cp_async16(slot0 + s * 4096, base + (size_t)s * HWSZ);
        cp_commit();
    }

    int4 t = *reinterpret_cast<const int4*>(tgt + p);
    bool v0 = (unsigned)t.x < N_ORI;
    bool v1 = (unsigned)t.y < N_ORI;
    bool v2 = (unsigned)t.z < N_ORI;
    bool v3 = (unsigned)t.w < N_ORI;

    unsigned long long m0 = v0 ? ((unsigned long long)smask_hi[t.x] << 32 | smask_lo[t.x]) : 0ull;
    unsigned long long m1 = v1 ? ((unsigned long long)smask_hi[t.y] << 32 | smask_lo[t.y]) : 0ull;
    unsigned long long m2 = v2 ? ((unsigned long long)smask_hi[t.z] << 32 | smask_lo[t.z]) : 0ull;
    unsigned long long m3 = v3 ? ((unsigned long long)smask_hi[t.w] << 32 | smask_lo[t.w]) : 0ull;

    float a0 = 0.f, a1 = 0.f, a2 = 0.f, a3 = 0.f;   // all-channel sums
    float s0 = 0.f, s1 = 0.f, s2 = 0.f, s3 = 0.f;   // target-group sums

    #pragma unroll 8
    for (int c = 0; c < CC; ++c) {
        cp_wait<STAGES - 1>();                       // oldest stage (channel c) ready
        int slot = (c & (STAGES - 1));
        float4 v = sbuf[slot * 256 + tid];           // self-consume, no barrier

        float e0 = __expf(v.x), e1 = __expf(v.y);
        float e2 = __expf(v.z), e3 = __expf(v.w);
        a0 += e0; a1 += e1; a2 += e2; a3 += e3;
        if ((m0 >> c) & 1ull) s0 += e0;
        if ((m1 >> c) & 1ull) s1 += e1;
        if ((m2 >> c) & 1ull) s2 += e2;
        if ((m3 >> c) & 1ull) s3 += e3;

        int nc = c + STAGES;
        if (nc < CC)
            cp_async16(slot0 + slot * 4096, base + (size_t)nc * HWSZ);
        cp_commit();                                 // empty groups in the tail are fine
    }

    float lsum = 0.0f;
    int   lcnt = 0;
    // -(log(s_t) - log(s_all)) = log(s_all) - log(s_t)
    if (v0) { lsum += __logf(a0) - __logf(s0); lcnt++; }
    if (v1) { lsum += __logf(a1) - __logf(s1); lcnt++; }
    if (v2) { lsum += __logf(a2) - __logf(s2); lcnt++; }
    if (v3) { lsum += __logf(a3) - __logf(s3); lcnt++; }

    // Warp reduce
    #pragma unroll
    for (int o = 16; o > 0; o >>= 1) {
        lsum += __shfl_down_sync(0xFFFFFFFFu, lsum, o);
        lcnt += __shfl_down_sync(0xFFFFFFFFu, lcnt, o);
    }

    __shared__ float wsum[8];
    __shared__ int   wcnt[8];
    int wid = tid >> 5;
    int lid = tid & 31;
    if (lid == 0) { wsum[wid] = lsum; wcnt[wid] = lcnt; }
    __syncthreads();

    __shared__ bool s_last;
    if (tid == 0) {
        float bs = 0.f; int bc = 0;
        #pragma unroll
        for (int w = 0; w < 8; ++w) { bs += wsum[w]; bc += wcnt[w]; }
        atomicAdd(&g_sum, (double)bs);
        atomicAdd(&g_cnt, (unsigned long long)bc);
        __threadfence();
        unsigned int ticket = atomicAdd(&g_ticket, 1u);
        s_last = (ticket == NBLOCKS - 1);
    }
    __syncthreads();

    if (s_last && tid == 0) {
        double sum = atomicAdd(&g_sum, 0.0);                    // acquire-read
        unsigned long long n = atomicAdd(&g_cnt, 0ull);
        if (n < 1ull) n = 1ull;
        out[0] = (float)(sum / (double)n);
        // Reset scratch for the next graph replay (deterministic).
        g_sum = 0.0;
        g_cnt = 0ull;
        __threadfence();
        g_ticket = 0u;
    }
}

extern "C" void kernel_launch(void* const* d_in, const int* in_sizes, int n_in,
                              void* d_out, int out_size) {
    const float* inp = (const float*)d_in[0];
    const int*   tgt = (const int*)d_in[1];
    const int*   gid = (const int*)d_in[2];
    float*       out = (float*)d_out;

    uce_kernel<<<NBLOCKS, 256>>>(inp, tgt, gid, out);
}

// round 6
// speedup vs baseline: 1.1620x; 1.0054x over previous
#include <cuda_runtime.h>

#define BB 4
#define CC 64
#define HH 512
#define WW 512
#define HWSZ (HH * WW)            // 262144
#define NPIX (BB * HWSZ)          // 1048576
#define NQUAD (NPIX / 4)          // 262144
#define N_ORI 20
#define NBLOCKS (NQUAD / 256)     // 1024
#define STAGES 8
#define IGN 255

// Scratch (allocation-free per harness rules). Statically zeroed for first
// run; the last block of each run resets them, keeping graph replays
// deterministic.
__device__ double g_sum = 0.0;
__device__ unsigned long long g_cnt = 0ull;
__device__ unsigned int g_ticket = 0u;

__device__ __forceinline__ void cp_async16(unsigned int saddr, const void* gptr) {
    asm volatile("cp.async.cg.shared.global [%0], [%1], 16;\n"
                 :: "r"(saddr), "l"(gptr) : "memory");
}
__device__ __forceinline__ void cp_commit() {
    asm volatile("cp.async.commit_group;\n" ::: "memory");
}
template <int N>
__device__ __forceinline__ void cp_wait() {
    asm volatile("cp.async.wait_group %0;\n" :: "n"(N) : "memory");
}

__global__ __launch_bounds__(256) void uce_kernel(
    const float* __restrict__ inp,   // [B, C, H, W] f32
    const int* __restrict__ tgt,     // [B, H, W] int32
    const int* __restrict__ gid,     // [C] int32
    float* __restrict__ out)
{
    __shared__ __align__(16) float4 sbuf[STAGES * 256];   // 32 KB ring
    __shared__ unsigned int smask_lo[N_ORI];
    __shared__ unsigned int smask_hi[N_ORI];

    int tid = threadIdx.x;
    if (tid < N_ORI) { smask_lo[tid] = 0u; smask_hi[tid] = 0u; }
    __syncthreads();
    if (tid < CC) {
        int g = gid[tid];
        if (g >= 0 && g < N_ORI) {
            if (tid < 32) atomicOr(&smask_lo[g], 1u << tid);
            else          atomicOr(&smask_hi[g], 1u << (tid - 32));
        }
    }
    __syncthreads();

    int q = blockIdx.x * 256 + tid;          // quad index (4 pixels/thread)
    int p  = q << 2;
    int b  = p >> 18;                        // p / HWSZ
    int hw = p & (HWSZ - 1);                 // multiple of 4 -> float4 aligned
    const float* base = inp + (size_t)b * (CC * HWSZ) + hw;

    // This thread's slot in stage 0 (stage s = +s*4096 bytes)
    unsigned int slot0 = (unsigned int)__cvta_generic_to_shared(&sbuf[tid]);

    // Prologue: fill all stages (channels 0..STAGES-1)
    #pragma unroll
    for (int s = 0; s < STAGES; ++s) {
        cp_async16(slot0 + s * 4096, base + (size_t)s * HWSZ);
        cp_commit();
    }

    int4 t = *reinterpret_cast<const int4*>(tgt + p);
    bool v0 = (unsigned)t.x < N_ORI;
    bool v1 = (unsigned)t.y < N_ORI;
    bool v2 = (unsigned)t.z < N_ORI;
    bool v3 = (unsigned)t.w < N_ORI;

    unsigned long long m0 = v0 ? ((unsigned long long)smask_hi[t.x] << 32 | smask_lo[t.x]) : 0ull;
    unsigned long long m1 = v1 ? ((unsigned long long)smask_hi[t.y] << 32 | smask_lo[t.y]) : 0ull;
    unsigned long long m2 = v2 ? ((unsigned long long)smask_hi[t.z] << 32 | smask_lo[t.z]) : 0ull;
    unsigned long long m3 = v3 ? ((unsigned long long)smask_hi[t.w] << 32 | smask_lo[t.w]) : 0ull;

    float a0 = 0.f, a1 = 0.f, a2 = 0.f, a3 = 0.f;   // all-channel sums
    float s0 = 0.f, s1 = 0.f, s2 = 0.f, s3 = 0.f;   // target-group sums

    #pragma unroll 8
    for (int c = 0; c < CC; ++c) {
        cp_wait<STAGES - 1>();                       // oldest stage (channel c) ready
        int slot = (c & (STAGES - 1));
        float4 v = sbuf[slot * 256 + tid];           // self-consume, no barrier

        float e0 = __expf(v.x), e1 = __expf(v.y);
        float e2 = __expf(v.z), e3 = __expf(v.w);
        a0 += e0; a1 += e1; a2 += e2; a3 += e3;
        if ((m0 >> c) & 1ull) s0 += e0;
        if ((m1 >> c) & 1ull) s1 += e1;
        if ((m2 >> c) & 1ull) s2 += e2;
        if ((m3 >> c) & 1ull) s3 += e3;

        int nc = c + STAGES;
        if (nc < CC)
            cp_async16(slot0 + slot * 4096, base + (size_t)nc * HWSZ);
        cp_commit();                                 // empty groups in the tail are fine
    }

    float lsum = 0.0f;
    int   lcnt = 0;
    // -(log(s_t) - log(s_all)) = log(s_all) - log(s_t)
    if (v0) { lsum += __logf(a0) - __logf(s0); lcnt++; }
    if (v1) { lsum += __logf(a1) - __logf(s1); lcnt++; }
    if (v2) { lsum += __logf(a2) - __logf(s2); lcnt++; }
    if (v3) { lsum += __logf(a3) - __logf(s3); lcnt++; }

    // Warp reduce
    #pragma unroll
    for (int o = 16; o > 0; o >>= 1) {
        lsum += __shfl_down_sync(0xFFFFFFFFu, lsum, o);
        lcnt += __shfl_down_sync(0xFFFFFFFFu, lcnt, o);
    }

    __shared__ float wsum[8];
    __shared__ int   wcnt[8];
    int wid = tid >> 5;
    int lid = tid & 31;
    if (lid == 0) { wsum[wid] = lsum; wcnt[wid] = lcnt; }
    __syncthreads();

    __shared__ bool s_last;
    if (tid == 0) {
        float bs = 0.f; int bc = 0;
        #pragma unroll
        for (int w = 0; w < 8; ++w) { bs += wsum[w]; bc += wcnt[w]; }
        atomicAdd(&g_sum, (double)bs);
        atomicAdd(&g_cnt, (unsigned long long)bc);
        __threadfence();
        unsigned int ticket = atomicAdd(&g_ticket, 1u);
        s_last = (ticket == NBLOCKS - 1);
    }
    __syncthreads();

    if (s_last && tid == 0) {
        double sum = atomicAdd(&g_sum, 0.0);                    // acquire-read
        unsigned long long n = atomicAdd(&g_cnt, 0ull);
        if (n < 1ull) n = 1ull;
        out[0] = (float)(sum / (double)n);
        // Reset scratch for the next graph replay (deterministic).
        g_sum = 0.0;
        g_cnt = 0ull;
        __threadfence();
        g_ticket = 0u;
    }
}

extern "C" void kernel_launch(void* const* d_in, const int* in_sizes, int n_in,
                              void* d_out, int out_size) {
    const float* inp = (const float*)d_in[0];
    const int*   tgt = (const int*)d_in[1];
    const int*   gid = (const int*)d_in[2];
    float*       out = (float*)d_out;

    uce_kernel<<<NBLOCKS, 256>>>(inp, tgt, gid, out);
}